// round 17
// baseline (speedup 1.0000x reference)
#include <cuda_runtime.h>
#include <cuda_bf16.h>
#include <cstdint>

#define B_     8
#define S_     1024
#define D_     512
#define H_     8
#define HD_    64
#define FF_    2048
#define STEPS_ 64
#define CAP_   1088
#define MTOK   (B_*S_)     /* 8192 */
#define MDEC   (STEPS_*B_) /* 512 */
#define MALL   (MTOK+MDEC) /* 8704 */
#define KPITCH 36
#define ATTN_SMEM (4*64*KPITCH*4)

// weight split-array offsets (packed words)
#define OFF_QKV 0
#define OFF_OUT 393216
#define OFF_W1  524288
#define OFF_W2  1048576
#define WTOTAL  1572864

// ---------------- device scratch ----------------
__device__ float g_qkv [MTOK*1536];
__device__ float g_qkvdec[MDEC*1536];
__device__ float g_pre [MTOK*D_];
__device__ float g_h   [MTOK*D_];
__device__ float g_kc  [B_*CAP_*D_];
__device__ float g_vc  [B_*CAP_*D_];
__device__ float g_dpre [MDEC*D_];
__device__ float g_dhb  [MDEC*D_];
__device__ unsigned g_wh[WTOTAL];
__device__ unsigned g_wl[WTOTAL];
__device__ unsigned g_attnh[MTOK*256], g_attnl[MTOK*256];
__device__ unsigned g_hbh [MTOK*256], g_hbl [MTOK*256];
__device__ unsigned g_hffh[MTOK*1024], g_hffl[MTOK*1024];
__device__ unsigned g_dattnh[MDEC*256], g_dattnl[MDEC*256];
__device__ unsigned g_dhbh[MDEC*256], g_dhbl[MDEC*256];
__device__ unsigned g_dhffh[MDEC*1024], g_dhffl[MDEC*1024];

// ---------------- helpers ----------------
__device__ __forceinline__ float warpRedSum(float v) {
#pragma unroll
    for (int o = 16; o; o >>= 1) v += __shfl_xor_sync(0xffffffffu, v, o);
    return v;
}
__device__ __forceinline__ unsigned pack_bf2(float lo, float hi) {
    unsigned r;
    asm("cvt.rn.bf16x2.f32 %0, %1, %2;" : "=r"(r) : "f"(hi), "f"(lo));
    return r;
}
__device__ __forceinline__ float2 unpack_bf2(unsigned u) {
    __nv_bfloat162 t;
    *(unsigned*)&t = u;
    return make_float2(__bfloat162float(t.x), __bfloat162float(t.y));
}
__device__ __forceinline__ void split2(float a, float b, unsigned& h, unsigned& l) {
    h = pack_bf2(a, b);
    float2 f = unpack_bf2(h);
    l = pack_bf2(a - f.x, b - f.y);
}

__device__ __forceinline__ void mma1(unsigned a0, unsigned a1, unsigned a2, unsigned a3,
                                     unsigned b0, unsigned b1, float c[4]) {
    asm volatile(
        "mma.sync.aligned.m16n8k16.row.col.f32.bf16.bf16.f32 "
        "{%0,%1,%2,%3}, {%4,%5,%6,%7}, {%8,%9}, {%0,%1,%2,%3};"
        : "+f"(c[0]), "+f"(c[1]), "+f"(c[2]), "+f"(c[3])
        : "r"(a0), "r"(a1), "r"(a2), "r"(a3), "r"(b0), "r"(b1));
}
__device__ __forceinline__ void mma_bf(const unsigned a[4][4],
                                       const unsigned b[4][2],
                                       float acc[4][4][4])
{
#pragma unroll
    for (int mt = 0; mt < 4; mt++)
#pragma unroll
        for (int nt = 0; nt < 4; nt++)
            mma1(a[mt][0], a[mt][1], a[mt][2], a[mt][3],
                 b[nt][0], b[nt][1], acc[mt][nt]);
}

// ---------------- weight split kernel ----------------
__global__ void __launch_bounds__(256) splitw(const float* __restrict__ src,
                                              unsigned* __restrict__ dh,
                                              unsigned* __restrict__ dl, int npairs)
{
    const int i = blockIdx.x * 256 + threadIdx.x;
    if (i < npairs) {
        float2 v = *(const float2*)(src + 2 * i);
        split2(v.x, v.y, dh[i], dl[i]);
    }
}

// ---------------- SGEMM (NT), bf16x3 MMA ----------------
// ASPLIT: A pre-split (AH/AL packed, K/2 words/row). OSPLIT: 1 -> write packed
// CH/CL only. KVOUT==3: combined QKV map (A/A2 fp32, C/C2 fp32, K/V scatter).
template<int BIAS, int RELU, int RES, int KVOUT, int ASPLIT, int OSPLIT>
__global__ void __launch_bounds__(256, 2) sgemm_nt(
    const float* __restrict__ A, const float* __restrict__ A2,
    const unsigned* __restrict__ AH, const unsigned* __restrict__ AL,
    const unsigned* __restrict__ BmH, const unsigned* __restrict__ BmL,
    const float* __restrict__ bias, const float* __restrict__ R,
    float* __restrict__ C, float* __restrict__ C2,
    unsigned* __restrict__ CH, unsigned* __restrict__ CL,
    int M, int N, int K,
    float* __restrict__ kc, float* __restrict__ vc)
{
    __shared__ unsigned AhS[128][12], AlS[128][12];
    __shared__ unsigned BhS[128][12], BlS[128][12];
    const int tid = threadIdx.x;
    const int m0 = blockIdx.y * 128;
    const int n0 = blockIdx.x * 128;
    const int w = tid >> 5, lane = tid & 31;
    const int wm0 = (w >> 2) * 64;
    const int wn0 = (w & 3) * 32;
    const int g = lane >> 2, tq = lane & 3;
    const int lrow = tid >> 2;
    const int lk4  = (tid & 3) * 4;
    const int lk2  = (tid & 3) * 2;
    const int Kw = K >> 1;

    const bool dec = (KVOUT == 3) && (m0 >= MTOK);

    const float *Ap0 = nullptr, *Ap1 = nullptr;
    const unsigned *AH0 = nullptr, *AH1 = nullptr, *AL0 = nullptr, *AL1 = nullptr;
    if (ASPLIT) {
        AH0 = AH + (size_t)(m0 + lrow)      * Kw + lk2;
        AH1 = AH + (size_t)(m0 + lrow + 64) * Kw + lk2;
        AL0 = AL + (size_t)(m0 + lrow)      * Kw + lk2;
        AL1 = AL + (size_t)(m0 + lrow + 64) * Kw + lk2;
    } else {
        const float* Ab = dec ? (A2 + (size_t)(m0 - MTOK) * K)
                              : (A  + (size_t)m0 * K);
        Ap0 = Ab + (size_t)lrow * K + lk4;
        Ap1 = Ab + (size_t)(lrow + 64) * K + lk4;
    }
    const unsigned* BH0 = BmH + (size_t)(n0 + lrow)      * Kw + lk2;
    const unsigned* BH1 = BmH + (size_t)(n0 + lrow + 64) * Kw + lk2;
    const unsigned* BL0 = BmL + (size_t)(n0 + lrow)      * Kw + lk2;
    const unsigned* BL1 = BmL + (size_t)(n0 + lrow + 64) * Kw + lk2;

    float acc[4][4][4];
#pragma unroll
    for (int i = 0; i < 4; i++)
#pragma unroll
        for (int j = 0; j < 4; j++)
#pragma unroll
            for (int q = 0; q < 4; q++) acc[i][j][q] = 0.f;

    float4 pa0, pa1;
    uint2 pah0, pah1, pal0, pal1;
    if (ASPLIT) {
        pah0 = *(const uint2*)(AH0); pah1 = *(const uint2*)(AH1);
        pal0 = *(const uint2*)(AL0); pal1 = *(const uint2*)(AL1);
    } else {
        pa0 = *(const float4*)(Ap0); pa1 = *(const float4*)(Ap1);
    }
    uint2 pbh0 = *(const uint2*)(BH0);
    uint2 pbh1 = *(const uint2*)(BH1);
    uint2 pbl0 = *(const uint2*)(BL0);
    uint2 pbl1 = *(const uint2*)(BL1);

    for (int k0 = 0; k0 < K; k0 += 16) {
        if (ASPLIT) {
            AhS[lrow][lk2]          = pah0.x;
            AhS[lrow][lk2 + 1]      = pah0.y;
            AhS[lrow + 64][lk2]     = pah1.x;
            AhS[lrow + 64][lk2 + 1] = pah1.y;
            AlS[lrow][lk2]          = pal0.x;
            AlS[lrow][lk2 + 1]      = pal0.y;
            AlS[lrow + 64][lk2]     = pal1.x;
            AlS[lrow + 64][lk2 + 1] = pal1.y;
        } else {
            unsigned h, l;
            split2(pa0.x, pa0.y, h, l);
            AhS[lrow][lk2] = h;          AlS[lrow][lk2] = l;
            split2(pa0.z, pa0.w, h, l);
            AhS[lrow][lk2 + 1] = h;      AlS[lrow][lk2 + 1] = l;
            split2(pa1.x, pa1.y, h, l);
            AhS[lrow + 64][lk2] = h;     AlS[lrow + 64][lk2] = l;
            split2(pa1.z, pa1.w, h, l);
            AhS[lrow + 64][lk2 + 1] = h; AlS[lrow + 64][lk2 + 1] = l;
        }
        BhS[lrow][lk2]          = pbh0.x;
        BhS[lrow][lk2 + 1]      = pbh0.y;
        BhS[lrow + 64][lk2]     = pbh1.x;
        BhS[lrow + 64][lk2 + 1] = pbh1.y;
        BlS[lrow][lk2]          = pbl0.x;
        BlS[lrow][lk2 + 1]      = pbl0.y;
        BlS[lrow + 64][lk2]     = pbl1.x;
        BlS[lrow + 64][lk2 + 1] = pbl1.y;
        __syncthreads();
        if (k0 + 16 < K) {
            const int kw = (k0 >> 1) + 8;
            if (ASPLIT) {
                pah0 = *(const uint2*)(AH0 + kw); pah1 = *(const uint2*)(AH1 + kw);
                pal0 = *(const uint2*)(AL0 + kw); pal1 = *(const uint2*)(AL1 + kw);
            } else {
                pa0 = *(const float4*)(Ap0 + k0 + 16);
                pa1 = *(const float4*)(Ap1 + k0 + 16);
            }
            pbh0 = *(const uint2*)(BH0 + kw);
            pbh1 = *(const uint2*)(BH1 + kw);
            pbl0 = *(const uint2*)(BL0 + kw);
            pbl1 = *(const uint2*)(BL1 + kw);
        }
        {
            unsigned ah[4][4], bh[4][2];
#pragma unroll
            for (int mt = 0; mt < 4; mt++) {
                const int rA = wm0 + mt * 16 + g;
                ah[mt][0] = AhS[rA][tq];
                ah[mt][1] = AhS[rA + 8][tq];
                ah[mt][2] = AhS[rA][4 + tq];
                ah[mt][3] = AhS[rA + 8][4 + tq];
            }
#pragma unroll
            for (int nt = 0; nt < 4; nt++) {
                const int rB = wn0 + nt * 8 + g;
                bh[nt][0] = BhS[rB][tq];
                bh[nt][1] = BhS[rB][4 + tq];
            }
            mma_bf(ah, bh, acc);
            {
                unsigned bl[4][2];
#pragma unroll
                for (int nt = 0; nt < 4; nt++) {
                    const int rB = wn0 + nt * 8 + g;
                    bl[nt][0] = BlS[rB][tq];
                    bl[nt][1] = BlS[rB][4 + tq];
                }
                mma_bf(ah, bl, acc);
            }
            {
                unsigned al[4][4];
#pragma unroll
                for (int mt = 0; mt < 4; mt++) {
                    const int rA = wm0 + mt * 16 + g;
                    al[mt][0] = AlS[rA][tq];
                    al[mt][1] = AlS[rA + 8][tq];
                    al[mt][2] = AlS[rA][4 + tq];
                    al[mt][3] = AlS[rA + 8][4 + tq];
                }
                mma_bf(al, bh, acc);
            }
        }
        __syncthreads();
    }

    const int Nw = N >> 1;
#pragma unroll
    for (int nt = 0; nt < 4; nt++) {
        const int col = n0 + wn0 + nt * 8 + tq * 2;
        const float b0v = BIAS ? bias[col] : 0.f;
        const float b1v = BIAS ? bias[col + 1] : 0.f;
#pragma unroll
        for (int mt = 0; mt < 4; mt++) {
#pragma unroll
            for (int rh = 0; rh < 2; rh++) {
                const int row = m0 + wm0 + mt * 16 + g + rh * 8;
                const int rl = dec ? row - MTOK : row;
                float t0 = acc[mt][nt][rh * 2 + 0] + b0v;
                float t1 = acc[mt][nt][rh * 2 + 1] + b1v;
                if (RES) {
                    float2 r = *(const float2*)(R + (size_t)row * N + col);
                    t0 += r.x; t1 += r.y;
                }
                if (RELU) { t0 = fmaxf(t0, 0.f); t1 = fmaxf(t1, 0.f); }
                if (OSPLIT) {
                    unsigned h, l;
                    split2(t0, t1, h, l);
                    CH[(size_t)row * Nw + (col >> 1)] = h;
                    CL[(size_t)row * Nw + (col >> 1)] = l;
                } else {
                    float* Cb = dec ? C2 : C;
                    float2 v; v.x = t0; v.y = t1;
                    *(float2*)(Cb + (size_t)rl * N + col) = v;
                    if (KVOUT == 3 && col >= 512) {
                        int bb, ss;
                        if (!dec) { bb = rl >> 10; ss = rl & 1023; }
                        else      { bb = rl & 7;   ss = S_ + (rl >> 3); }
                        float* dst = (col < 1024)
                            ? kc + ((size_t)(bb * CAP_ + ss) * 512 + (col - 512))
                            : vc + ((size_t)(bb * CAP_ + ss) * 512 + (col - 1024));
                        *(float2*)dst = v;
                    }
                }
            }
        }
    }
}

// ---------------- tensor-core flash attention (packed split output) ---------
__device__ __forceinline__ void flash64_mma(
    const float* __restrict__ qbase, size_t qstride,
    const float* __restrict__ kbase, size_t kstride,
    const float* __restrict__ vbase, size_t vstride,
    unsigned* __restrict__ ohbase, unsigned* __restrict__ olbase, size_t wstride,
    int ntiles, int diagTile, unsigned* sm, int tid)
{
    unsigned* Kh = sm;
    unsigned* Kl = Kh + 64 * KPITCH;
    unsigned* Vh = Kl + 64 * KPITCH;
    unsigned* Vl = Vh + 64 * KPITCH;
    __nv_bfloat16* vhh = (__nv_bfloat16*)Vh;
    __nv_bfloat16* vlh = (__nv_bfloat16*)Vl;

    const int w = tid >> 5, lane = tid & 31;
    const int g = lane >> 2, tq = lane & 3;
    const int wq0 = w * 16;
    const int strow = tid >> 1, sths = tid & 1;

    unsigned qh[4][4], ql[4][4];
    {
        const float* r0p = qbase + (size_t)(wq0 + g) * qstride;
        const float* r1p = qbase + (size_t)(wq0 + g + 8) * qstride;
#pragma unroll
        for (int s = 0; s < 4; s++)
#pragma unroll
            for (int part = 0; part < 4; part++) {
                const float* rp = (part & 1) ? r1p : r0p;
                const int col = 16 * s + ((part >> 1) ? 8 : 0) + 2 * tq;
                float2 v = *(const float2*)(rp + col);
                split2(v.x * 0.125f, v.y * 0.125f, qh[s][part], ql[s][part]);
            }
    }

    float oacc[8][4];
#pragma unroll
    for (int j = 0; j < 8; j++)
#pragma unroll
        for (int q = 0; q < 4; q++) oacc[j][q] = 0.f;
    float mrow0 = -1e30f, mrow1 = -1e30f, lrow0 = 0.f, lrow1 = 0.f;

    for (int tile = 0; tile < ntiles; ++tile) {
        const int j0 = tile * 64;
        __syncthreads();
#pragma unroll
        for (int i = 0; i < 8; i++) {
            float4 kv = *(const float4*)(kbase + (size_t)(j0 + strow) * kstride
                                         + sths * 32 + i * 4);
            const int wi = strow * KPITCH + sths * 16 + i * 2;
            split2(kv.x, kv.y, Kh[wi], Kl[wi]);
            split2(kv.z, kv.w, Kh[wi + 1], Kl[wi + 1]);
            float4 vv = *(const float4*)(vbase + (size_t)(j0 + strow) * vstride
                                         + sths * 32 + i * 4);
            const float* vp = (const float*)&vv;
#pragma unroll
            for (int jj = 0; jj < 4; jj++) {
                const int d = sths * 32 + i * 4 + jj;
                __nv_bfloat16 hb = __float2bfloat16(vp[jj]);
                vhh[d * (2 * KPITCH) + strow] = hb;
                vlh[d * (2 * KPITCH) + strow] =
                    __float2bfloat16(vp[jj] - __bfloat162float(hb));
            }
        }
        __syncthreads();

        float sacc[8][4];
#pragma unroll
        for (int j = 0; j < 8; j++)
#pragma unroll
            for (int q = 0; q < 4; q++) sacc[j][q] = 0.f;
#pragma unroll
        for (int s = 0; s < 4; s++)
#pragma unroll
            for (int j = 0; j < 8; j++) {
                const int base = (8 * j + g) * KPITCH + 8 * s + tq;
                unsigned kb0 = Kh[base], kb1 = Kh[base + 4];
                mma1(qh[s][0], qh[s][1], qh[s][2], qh[s][3], kb0, kb1, sacc[j]);
                mma1(ql[s][0], ql[s][1], ql[s][2], ql[s][3], kb0, kb1, sacc[j]);
                unsigned lb0 = Kl[base], lb1 = Kl[base + 4];
                mma1(qh[s][0], qh[s][1], qh[s][2], qh[s][3], lb0, lb1, sacc[j]);
            }

        if (tile == diagTile) {
            const int row0 = wq0 + g, row1 = row0 + 8;
#pragma unroll
            for (int j = 0; j < 8; j++) {
                const int c = 8 * j + 2 * tq;
                if (c > row0)     sacc[j][0] = -1e30f;
                if (c + 1 > row0) sacc[j][1] = -1e30f;
                if (c > row1)     sacc[j][2] = -1e30f;
                if (c + 1 > row1) sacc[j][3] = -1e30f;
            }
        }

        float m0 = -1e30f, m1 = -1e30f;
#pragma unroll
        for (int j = 0; j < 8; j++) {
            m0 = fmaxf(m0, fmaxf(sacc[j][0], sacc[j][1]));
            m1 = fmaxf(m1, fmaxf(sacc[j][2], sacc[j][3]));
        }
        m0 = fmaxf(m0, __shfl_xor_sync(0xffffffffu, m0, 1));
        m0 = fmaxf(m0, __shfl_xor_sync(0xffffffffu, m0, 2));
        m1 = fmaxf(m1, __shfl_xor_sync(0xffffffffu, m1, 1));
        m1 = fmaxf(m1, __shfl_xor_sync(0xffffffffu, m1, 2));
        const float mn0 = fmaxf(mrow0, m0), mn1 = fmaxf(mrow1, m1);
        const float al0 = __expf(mrow0 - mn0), al1 = __expf(mrow1 - mn1);
        float ls0 = 0.f, ls1 = 0.f;
        unsigned ph0[8], ph1[8], pl0[8], pl1[8];
#pragma unroll
        for (int j = 0; j < 8; j++) {
            float p0 = __expf(sacc[j][0] - mn0);
            float p1 = __expf(sacc[j][1] - mn0);
            float p2 = __expf(sacc[j][2] - mn1);
            float p3 = __expf(sacc[j][3] - mn1);
            ls0 += p0 + p1; ls1 += p2 + p3;
            split2(p0, p1, ph0[j], pl0[j]);
            split2(p2, p3, ph1[j], pl1[j]);
        }
        ls0 += __shfl_xor_sync(0xffffffffu, ls0, 1);
        ls0 += __shfl_xor_sync(0xffffffffu, ls0, 2);
        ls1 += __shfl_xor_sync(0xffffffffu, ls1, 1);
        ls1 += __shfl_xor_sync(0xffffffffu, ls1, 2);
        lrow0 = lrow0 * al0 + ls0; mrow0 = mn0;
        lrow1 = lrow1 * al1 + ls1; mrow1 = mn1;
#pragma unroll
        for (int j = 0; j < 8; j++) {
            oacc[j][0] *= al0; oacc[j][1] *= al0;
            oacc[j][2] *= al1; oacc[j][3] *= al1;
        }

#pragma unroll
        for (int s = 0; s < 4; s++) {
            const unsigned a0 = ph0[2 * s],     a1 = ph1[2 * s];
            const unsigned a2 = ph0[2 * s + 1], a3 = ph1[2 * s + 1];
            const unsigned c0 = pl0[2 * s],     c1 = pl1[2 * s];
            const unsigned c2 = pl0[2 * s + 1], c3 = pl1[2 * s + 1];
#pragma unroll
            for (int j = 0; j < 8; j++) {
                const int base = (8 * j + g) * KPITCH + 8 * s + tq;
                unsigned vb0 = Vh[base], vb1 = Vh[base + 4];
                mma1(a0, a1, a2, a3, vb0, vb1, oacc[j]);
                mma1(c0, c1, c2, c3, vb0, vb1, oacc[j]);
                unsigned wl0 = Vl[base], wl1 = Vl[base + 4];
                mma1(a0, a1, a2, a3, wl0, wl1, oacc[j]);
            }
        }
    }

    const float inv0 = 1.f / lrow0, inv1 = 1.f / lrow1;
#pragma unroll
    for (int j = 0; j < 8; j++) {
        unsigned h, l;
        split2(oacc[j][0] * inv0, oacc[j][1] * inv0, h, l);
        ohbase[(size_t)(wq0 + g) * wstride + 4 * j + tq] = h;
        olbase[(size_t)(wq0 + g) * wstride + 4 * j + tq] = l;
        split2(oacc[j][2] * inv1, oacc[j][3] * inv1, h, l);
        ohbase[(size_t)(wq0 + g + 8) * wstride + 4 * j + tq] = h;
        olbase[(size_t)(wq0 + g + 8) * wstride + 4 * j + tq] = l;
    }
}

__global__ void __launch_bounds__(128, 3) attn_prefill(const float* __restrict__ qkv,
                                                       unsigned* __restrict__ ah,
                                                       unsigned* __restrict__ al)
{
    extern __shared__ unsigned smu[];
    const int b  = blockIdx.y >> 3;
    const int h  = blockIdx.y & 7;
    const int l0 = blockIdx.x * 64;
    const size_t rowbase = (size_t)(b * S_) * 1536;
    flash64_mma(qkv + rowbase + (size_t)l0 * 1536 + h * 64, 1536,
                qkv + rowbase + 512 + h * 64, 1536,
                qkv + rowbase + 1024 + h * 64, 1536,
                ah + (size_t)(b * S_ + l0) * 256 + h * 32,
                al + (size_t)(b * S_ + l0) * 256 + h * 32, 256,
                (l0 >> 6) + 1, l0 >> 6, smu, threadIdx.x);
}

__global__ void __launch_bounds__(128, 3) attn_decode(const float* __restrict__ qdec,
                                                      const float* __restrict__ kc,
                                                      const float* __restrict__ vc,
                                                      unsigned* __restrict__ ah,
                                                      unsigned* __restrict__ al)
{
    extern __shared__ unsigned smu[];
    const int b = blockIdx.x >> 3;
    const int h = blockIdx.x & 7;
    flash64_mma(qdec + (size_t)b * 1536 + h * 64, 8 * 1536,
                kc + (size_t)b * CAP_ * 512 + h * 64, 512,
                vc + (size_t)b * CAP_ * 512 + h * 64, 512,
                ah + (size_t)b * 256 + h * 32,
                al + (size_t)b * 256 + h * 32, 8 * 256,
                CAP_ / 64, (CAP_ / 64) - 1, smu, threadIdx.x);
}

// ---------------- LayerNorm (float2 per thread) ----------------
template<int MODE, int EMITS>
__global__ void __launch_bounds__(256) ln_rows(const float* __restrict__ in,
                                               const float* __restrict__ g,
                                               const float* __restrict__ be,
                                               float* __restrict__ out,
                                               unsigned* __restrict__ oh,
                                               unsigned* __restrict__ ol)
{
    const int r = blockIdx.x;
    const int tid = threadIdx.x;
    float2 v = *(const float2*)(in + (size_t)r * 512 + 2 * tid);
    float s  = warpRedSum(v.x + v.y);
    float s2 = warpRedSum(v.x * v.x + v.y * v.y);
    __shared__ float r1[8], r2[8];
    __shared__ float smu2, srs;
    const int w = tid >> 5, lane = tid & 31;
    if (lane == 0) { r1[w] = s; r2[w] = s2; }
    __syncthreads();
    if (tid == 0) {
        float S = 0.f, S2 = 0.f;
#pragma unroll
        for (int i = 0; i < 8; i++) { S += r1[i]; S2 += r2[i]; }
        float mu  = S * (1.f / 512.f);
        float var = S2 * (1.f / 512.f) - mu * mu;
        smu2 = mu; srs = rsqrtf(var + 1e-5f);
    }
    __syncthreads();
    float2 gw = *(const float2*)(g + 2 * tid);
    float2 gb = *(const float2*)(be + 2 * tid);
    float o0 = (v.x - smu2) * srs * gw.x + gb.x;
    float o1 = (v.y - smu2) * srs * gw.y + gb.y;
    int orow;
    if (MODE == 0)      orow = r;
    else if (MODE == 1) orow = r + (r >> 10) * 64;
    else                orow = (r & 7) * CAP_ + S_ + (r >> 3);
    float2 ov; ov.x = o0; ov.y = o1;
    *(float2*)(out + (size_t)orow * 512 + 2 * tid) = ov;
    if (EMITS) {
        unsigned h, l;
        split2(o0, o1, h, l);
        oh[(size_t)r * 256 + tid] = h;
        ol[(size_t)r * 256 + tid] = l;
    }
}

// ---------------- host launcher ----------------
struct ScratchPtrs {
    float *Qkv, *Qdec, *Pre, *Hb, *Kc, *Vc, *Dpre, *Dhb;
    unsigned *Wh, *Wl;
    unsigned *AtH, *AtL, *HbH, *HbL, *HfH, *HfL;
    unsigned *DAtH, *DAtL, *DHbH, *DHbL, *DHfH, *DHfL;
    cudaStream_t sDec;
    cudaEvent_t evFork, evQkv, evDec, evSplit;
};

static const ScratchPtrs& get_scratch() {
    static ScratchPtrs p;
    static bool init = false;
    if (!init) {
        cudaGetSymbolAddress((void**)&p.Qkv,  g_qkv);
        cudaGetSymbolAddress((void**)&p.Qdec, g_qkvdec);
        cudaGetSymbolAddress((void**)&p.Pre,  g_pre);
        cudaGetSymbolAddress((void**)&p.Hb,   g_h);
        cudaGetSymbolAddress((void**)&p.Kc,   g_kc);
        cudaGetSymbolAddress((void**)&p.Vc,   g_vc);
        cudaGetSymbolAddress((void**)&p.Dpre, g_dpre);
        cudaGetSymbolAddress((void**)&p.Dhb,  g_dhb);
        cudaGetSymbolAddress((void**)&p.Wh,   g_wh);
        cudaGetSymbolAddress((void**)&p.Wl,   g_wl);
        cudaGetSymbolAddress((void**)&p.AtH,  g_attnh);
        cudaGetSymbolAddress((void**)&p.AtL,  g_attnl);
        cudaGetSymbolAddress((void**)&p.HbH,  g_hbh);
        cudaGetSymbolAddress((void**)&p.HbL,  g_hbl);
        cudaGetSymbolAddress((void**)&p.HfH,  g_hffh);
        cudaGetSymbolAddress((void**)&p.HfL,  g_hffl);
        cudaGetSymbolAddress((void**)&p.DAtH, g_dattnh);
        cudaGetSymbolAddress((void**)&p.DAtL, g_dattnl);
        cudaGetSymbolAddress((void**)&p.DHbH, g_dhbh);
        cudaGetSymbolAddress((void**)&p.DHbL, g_dhbl);
        cudaGetSymbolAddress((void**)&p.DHfH, g_dhffh);
        cudaGetSymbolAddress((void**)&p.DHfL, g_dhffl);
        cudaFuncSetAttribute(attn_prefill,
                             cudaFuncAttributeMaxDynamicSharedMemorySize, ATTN_SMEM);
        cudaFuncSetAttribute(attn_decode,
                             cudaFuncAttributeMaxDynamicSharedMemorySize, ATTN_SMEM);
        cudaStreamCreateWithFlags(&p.sDec, cudaStreamNonBlocking);
        cudaEventCreateWithFlags(&p.evFork, cudaEventDisableTiming);
        cudaEventCreateWithFlags(&p.evQkv, cudaEventDisableTiming);
        cudaEventCreateWithFlags(&p.evDec, cudaEventDisableTiming);
        cudaEventCreateWithFlags(&p.evSplit, cudaEventDisableTiming);
        init = true;
    }
    return p;
}

extern "C" void kernel_launch(void* const* d_in, const int* in_sizes, int n_in,
                              void* d_out, int out_size)
{
    (void)in_sizes; (void)n_in; (void)out_size;
    const float* x    = (const float*)d_in[0];
    const float* dx   = (const float*)d_in[1];
    // d_in[2] = causal_mask — unused, causality computed analytically
    const float* qkvW = (const float*)d_in[3];
    const float* qkvB = (const float*)d_in[4];
    const float* outW = (const float*)d_in[5];
    const float* outB = (const float*)d_in[6];
    const float* w1   = (const float*)d_in[7];
    const float* b1   = (const float*)d_in[8];
    const float* w2   = (const float*)d_in[9];
    const float* b2   = (const float*)d_in[10];
    const float* ln1w = (const float*)d_in[11];
    const float* ln1b = (const float*)d_in[12];
    const float* ln2w = (const float*)d_in[13];
    const float* ln2b = (const float*)d_in[14];
    float* out = (float*)d_out;

    const ScratchPtrs& sp = get_scratch();

    // ---- qkvW split (serial); fork side stream FIRST via event (capture-legal),
    //      then the other splits run on the side stream under the QKV GEMM ----
    splitw<<<(393216 + 255) / 256, 256>>>(qkvW, sp.Wh + OFF_QKV, sp.Wl + OFF_QKV, 393216);
    cudaEventRecord(sp.evFork, 0);
    cudaStreamWaitEvent(sp.sDec, sp.evFork, 0);
    splitw<<<(131072 + 255) / 256, 256, 0, sp.sDec>>>(outW, sp.Wh + OFF_OUT, sp.Wl + OFF_OUT, 131072);
    splitw<<<(524288 + 255) / 256, 256, 0, sp.sDec>>>(w1, sp.Wh + OFF_W1, sp.Wl + OFF_W1, 524288);
    splitw<<<(524288 + 255) / 256, 256, 0, sp.sDec>>>(w2, sp.Wh + OFF_W2, sp.Wl + OFF_W2, 524288);
    cudaEventRecord(sp.evSplit, sp.sDec);

    // ---- merged QKV GEMM (prefill + decode rows; seeds both KV regions) ----
    sgemm_nt<1,0,0,3,0,0><<<dim3(12, 68), 256>>>(
        x, dx, nullptr, nullptr, sp.Wh + OFF_QKV, sp.Wl + OFF_QKV, qkvB, nullptr,
        sp.Qkv, sp.Qdec, nullptr, nullptr, MALL, 1536, 512, sp.Kc, sp.Vc);
    cudaEventRecord(sp.evQkv, 0);

    // ---- decode chain (batched M=512) on the side stream ----
    cudaStreamWaitEvent(sp.sDec, sp.evQkv, 0);
    attn_decode<<<64, 128, ATTN_SMEM, sp.sDec>>>(sp.Qdec, sp.Kc, sp.Vc,
                                                 sp.DAtH, sp.DAtL);
    sgemm_nt<1,0,1,0,1,0><<<dim3(4, 4), 256, 0, sp.sDec>>>(
        nullptr, nullptr, sp.DAtH, sp.DAtL, sp.Wh + OFF_OUT, sp.Wl + OFF_OUT,
        outB, dx, sp.Dpre, nullptr, nullptr, nullptr, MDEC, 512, 512, nullptr, nullptr);
    ln_rows<0,1><<<MDEC, 256, 0, sp.sDec>>>(sp.Dpre, ln1w, ln1b, sp.Dhb,
                                            sp.DHbH, sp.DHbL);
    sgemm_nt<1,1,0,0,1,1><<<dim3(16, 4), 256, 0, sp.sDec>>>(
        nullptr, nullptr, sp.DHbH, sp.DHbL, sp.Wh + OFF_W1, sp.Wl + OFF_W1,
        b1, nullptr, nullptr, nullptr, sp.DHfH, sp.DHfL, MDEC, 2048, 512, nullptr, nullptr);
    sgemm_nt<1,0,1,0,1,0><<<dim3(4, 4), 256, 0, sp.sDec>>>(
        nullptr, nullptr, sp.DHfH, sp.DHfL, sp.Wh + OFF_W2, sp.Wl + OFF_W2,
        b2, sp.Dhb, sp.Dpre, nullptr, nullptr, nullptr, MDEC, 512, 2048, nullptr, nullptr);
    ln_rows<2,0><<<MDEC, 256, 0, sp.sDec>>>(sp.Dpre, ln2w, ln2b, out,
                                            nullptr, nullptr);
    cudaEventRecord(sp.evDec, sp.sDec);

    // ---- prefill chain on the main stream ----
    attn_prefill<<<dim3(16, 64), 128, ATTN_SMEM>>>(sp.Qkv, sp.AtH, sp.AtL);
    cudaStreamWaitEvent(0, sp.evSplit, 0);
    sgemm_nt<1,0,1,0,1,0><<<dim3(4, 64), 256>>>(
        nullptr, nullptr, sp.AtH, sp.AtL, sp.Wh + OFF_OUT, sp.Wl + OFF_OUT,
        outB, x, sp.Pre, nullptr, nullptr, nullptr, MTOK, 512, 512, nullptr, nullptr);
    ln_rows<0,1><<<MTOK, 256>>>(sp.Pre, ln1w, ln1b, sp.Hb, sp.HbH, sp.HbL);
    sgemm_nt<1,1,0,0,1,1><<<dim3(16, 64), 256>>>(
        nullptr, nullptr, sp.HbH, sp.HbL, sp.Wh + OFF_W1, sp.Wl + OFF_W1,
        b1, nullptr, nullptr, nullptr, sp.HfH, sp.HfL, MTOK, 2048, 512, nullptr, nullptr);
    sgemm_nt<1,0,1,0,1,0><<<dim3(4, 64), 256>>>(
        nullptr, nullptr, sp.HfH, sp.HfL, sp.Wh + OFF_W2, sp.Wl + OFF_W2,
        b2, sp.Hb, sp.Pre, nullptr, nullptr, nullptr, MTOK, 512, 2048, nullptr, nullptr);
    ln_rows<1,0><<<MTOK, 256>>>(sp.Pre, ln2w, ln2b, out, nullptr, nullptr);

    // ---- join ----
    cudaStreamWaitEvent(0, sp.evDec, 0);
}